// round 10
// baseline (speedup 1.0000x reference)
// R10: 512-thread CTA (4 warps/SMSP) to raise HMMA issue rate; warp tile 32x64.
#include <cuda_runtime.h>
#include <cuda_bf16.h>
#include <cstdint>
#include <cstddef>

#define N_TOK 8192
#define D_IN  4096
#define D_OUT 4096

// ---------------- scratch (static device arrays; no runtime alloc) ---------
__device__ __align__(16) __nv_bfloat16 g_Xb[(size_t)N_TOK * D_IN];   // 64 MB
__device__ __align__(16) __nv_bfloat16 g_Wb[(size_t)D_OUT * D_IN];   // 32 MB
__device__ unsigned g_absmax_u;

// ---------------- helpers ---------------------------------------------------
__device__ __forceinline__ uint32_t smem_u32(const void* p) {
    uint32_t a;
    asm("{ .reg .u64 t; cvta.to.shared.u64 t, %1; cvt.u32.u64 %0, t; }"
        : "=r"(a) : "l"(p));
    return a;
}

__device__ __forceinline__ void cp16(uint32_t dst, const void* src) {
    asm volatile("cp.async.cg.shared.global [%0], [%1], 16;" :: "r"(dst), "l"(src));
}

__device__ __forceinline__ void hmma16816(float* c, const uint32_t* a, const uint32_t* b) {
    asm volatile(
        "mma.sync.aligned.m16n8k16.row.col.f32.bf16.bf16.f32 "
        "{%0,%1,%2,%3}, {%4,%5,%6,%7}, {%8,%9}, {%0,%1,%2,%3};"
        : "+f"(c[0]), "+f"(c[1]), "+f"(c[2]), "+f"(c[3])
        : "r"(a[0]), "r"(a[1]), "r"(a[2]), "r"(a[3]), "r"(b[0]), "r"(b[1]));
}

__device__ __forceinline__ void ldm_x4(uint32_t* r, uint32_t addr) {
    asm volatile(
        "ldmatrix.sync.aligned.m8n8.x4.shared.b16 {%0,%1,%2,%3}, [%4];"
        : "=r"(r[0]), "=r"(r[1]), "=r"(r[2]), "=r"(r[3]) : "r"(addr));
}

// ---------------- pre-kernels ----------------------------------------------
__global__ void init_kernel() { g_absmax_u = 0u; }

__global__ void absmax_kernel(const float4* __restrict__ x, int n4) {
    float m = 0.f;
    for (int i = blockIdx.x * blockDim.x + threadIdx.x; i < n4;
         i += gridDim.x * blockDim.x) {
        float4 v = x[i];
        m = fmaxf(m, fmaxf(fmaxf(fabsf(v.x), fabsf(v.y)),
                           fmaxf(fabsf(v.z), fabsf(v.w))));
    }
#pragma unroll
    for (int o = 16; o > 0; o >>= 1)
        m = fmaxf(m, __shfl_xor_sync(0xffffffffu, m, o));
    __shared__ float red[8];
    if ((threadIdx.x & 31) == 0) red[threadIdx.x >> 5] = m;
    __syncthreads();
    if (threadIdx.x == 0) {
        float v = red[0];
#pragma unroll
        for (int i = 1; i < 8; ++i) v = fmaxf(v, red[i]);
        atomicMax(&g_absmax_u, __float_as_uint(v));   // values >= 0: bit-monotone
    }
}

__global__ void quant_kernel(const float4* __restrict__ x, int n4) {
    float am = __uint_as_float(g_absmax_u);
    float s = __fdiv_rn(am, 127.0f);            // exact IEEE div, matches reference
    if (s == 0.f) s = 1.0f;
    for (int i = blockIdx.x * blockDim.x + threadIdx.x; i < n4;
         i += gridDim.x * blockDim.x) {
        float4 v = x[i];
        float a0 = fminf(fmaxf(rintf(__fdiv_rn(v.x, s)), -128.f), 127.f);
        float a1 = fminf(fmaxf(rintf(__fdiv_rn(v.y, s)), -128.f), 127.f);
        float a2 = fminf(fmaxf(rintf(__fdiv_rn(v.z, s)), -128.f), 127.f);
        float a3 = fminf(fmaxf(rintf(__fdiv_rn(v.w, s)), -128.f), 127.f);
        __nv_bfloat162 h0 = __floats2bfloat162_rn(a0, a1);
        __nv_bfloat162 h1 = __floats2bfloat162_rn(a2, a3);
        uint2 u;
        u.x = *reinterpret_cast<uint32_t*>(&h0);
        u.y = *reinterpret_cast<uint32_t*>(&h1);
        reinterpret_cast<uint2*>(g_Xb)[i] = u;
    }
}

__global__ void wconv_kernel(const int4* __restrict__ w, int n4) {
    for (int i = blockIdx.x * blockDim.x + threadIdx.x; i < n4;
         i += gridDim.x * blockDim.x) {
        int4 v = w[i];   // values in {-1, 0, 1}
        __nv_bfloat162 h0 = __floats2bfloat162_rn((float)v.x, (float)v.y);
        __nv_bfloat162 h1 = __floats2bfloat162_rn((float)v.z, (float)v.w);
        uint2 u;
        u.x = *reinterpret_cast<uint32_t*>(&h0);
        u.y = *reinterpret_cast<uint32_t*>(&h1);
        reinterpret_cast<uint2*>(g_Wb)[i] = u;
    }
}

// ---------------- bf16 GEMM: C[8192,4096] = Xb @ Wb^T -----------------------
// CTA tile 128x256, 16 warps (4M x 4N), warp tile 32x64, 512 threads.
// K-chunk 64 elems, 3-stage cp.async pipeline, ks-double-buffered fragments.
#define BM 128
#define BN 256
#define BKE 64                            // K elems per chunk
#define BKB (BKE * 2)                     // 128 bytes per row per chunk
#define LDS_ROW 144                       // 128B data + 16B pad
#define A_STAGE (BM * LDS_ROW)            // 18432
#define B_STAGE (BN * LDS_ROW)            // 36864
#define STAGE_BYTES (A_STAGE + B_STAGE)   // 55296
#define STAGES 3
#define BIAS_OFF (STAGES * STAGE_BYTES)   // 165888
#define SMEM_TOTAL (BIAS_OFF + BN * 4)    // +1KB bias cache
#define NTHREADS 512

__device__ __forceinline__ void load_stage(uint32_t sbase, int s,
                                           const char* Ag, const char* Bg,
                                           int chunk, int tid) {
    uint32_t as = sbase + s * STAGE_BYTES;
    uint32_t bs = as + A_STAGE;
    const char* ag = Ag + (size_t)chunk * BKB;
    const char* bg = Bg + (size_t)chunk * BKB;
#pragma unroll
    for (int i = 0; i < 2; ++i) {         // A: 128 rows x 8 x 16B = 1024 cp16
        int j = i * NTHREADS + tid;
        int row = j >> 3, c = j & 7;
        cp16(as + row * LDS_ROW + c * 16, ag + (size_t)row * (D_IN * 2) + c * 16);
    }
#pragma unroll
    for (int i = 0; i < 4; ++i) {         // B: 256 rows x 8 x 16B = 2048 cp16
        int j = i * NTHREADS + tid;
        int row = j >> 3, c = j & 7;
        cp16(bs + row * LDS_ROW + c * 16, bg + (size_t)row * (D_IN * 2) + c * 16);
    }
    asm volatile("cp.async.commit_group;" ::: "memory");
}

__device__ __forceinline__ void load_frags(uint32_t stg, uint32_t aAddrBase,
                                           uint32_t bAddrBase, int ks,
                                           uint32_t a[2][4], uint32_t b[8][2]) {
#pragma unroll
    for (int mt = 0; mt < 2; ++mt)
        ldm_x4(a[mt], stg + aAddrBase + mt * (16 * LDS_ROW) + ks * 32);
#pragma unroll
    for (int ntp = 0; ntp < 4; ++ntp) {
        uint32_t r[4];
        ldm_x4(r, stg + bAddrBase + ntp * (16 * LDS_ROW) + ks * 32);
        b[ntp * 2 + 0][0] = r[0];
        b[ntp * 2 + 0][1] = r[1];
        b[ntp * 2 + 1][0] = r[2];
        b[ntp * 2 + 1][1] = r[3];
    }
}

__global__ void __launch_bounds__(NTHREADS, 1)
gemm_hmma(const float* __restrict__ bias, const float* __restrict__ wscale,
          float* __restrict__ out) {
    extern __shared__ char smem[];
    const uint32_t sbase = smem_u32(smem);
    const int tid = threadIdx.x;
    const int wid = tid >> 5, lane = tid & 31;
    const int g = lane >> 2, t = lane & 3;
    const int wm = wid & 3, wn = wid >> 2;           // 4 warps in M, 4 in N
    const int m0 = blockIdx.y * BM, n0 = blockIdx.x * BN;

    const char* Ag = (const char*)g_Xb + (size_t)m0 * (D_IN * 2);
    const char* Bg = (const char*)g_Wb + (size_t)n0 * (D_IN * 2);

    // stage bias into smem (coalesced, once)
    if (tid < BN) {
        float bv = bias[n0 + tid];
        *reinterpret_cast<float*>(smem + BIAS_OFF + tid * 4) = bv;
    }

    // A x4 (mt, ks): rows wm*32 + lane&15 (two 8-row matrices per 16 rows),
    //                byte-half (lane>>4)*16
    const uint32_t aAddrBase =
        (uint32_t)((wm * 32 + (lane & 15)) * LDS_ROW + ((lane >> 4) * 16));
    // B x4 (ntp, ks): cols wn*64, rows lane&7 + (lane>>4)*8, half (lane>>3 &1)*16
    const uint32_t bAddrBase =
        (uint32_t)(A_STAGE +
                   (wn * 64 + (lane & 7) + ((lane >> 4) * 8)) * LDS_ROW +
                   (((lane >> 3) & 1) * 16));

    float acc[2][8][4];
#pragma unroll
    for (int mt = 0; mt < 2; ++mt)
#pragma unroll
        for (int nt = 0; nt < 8; ++nt)
#pragma unroll
            for (int i = 0; i < 4; ++i) acc[mt][nt][i] = 0.f;

    // prologue: fill 2 stages
#pragma unroll
    for (int c = 0; c < 2; ++c) load_stage(sbase, c, Ag, Bg, c, tid);

    uint32_t abuf[2][2][4], bbuf[2][8][2];

    const int NCHUNK = D_IN / BKE;   // 64
    for (int c = 0; c < NCHUNK; ++c) {
        asm volatile("cp.async.wait_group %0;" :: "n"(1));
        __syncthreads();
        if (c + 2 < NCHUNK) {
            int s = c + 2;
            load_stage(sbase, s % STAGES, Ag, Bg, s, tid);
        }

        const uint32_t stg = sbase + (c % STAGES) * STAGE_BYTES;

        // prime ks=0
        load_frags(stg, aAddrBase, bAddrBase, 0, abuf[0], bbuf[0]);
#pragma unroll
        for (int ks = 0; ks < 4; ++ks) {
            const int cur = ks & 1;
            if (ks < 3)   // prefetch next ks while HMMAs below run
                load_frags(stg, aAddrBase, bAddrBase, ks + 1,
                           abuf[1 - cur], bbuf[1 - cur]);
#pragma unroll
            for (int mt = 0; mt < 2; ++mt)
#pragma unroll
                for (int nt = 0; nt < 8; ++nt)
                    hmma16816(acc[mt][nt], abuf[cur][mt], bbuf[cur][nt]);
        }
    }

    // epilogue: out = acc * (weight_scale * scale) + bias
    float am = __uint_as_float(g_absmax_u);
    float sc = __fdiv_rn(am, 127.0f);
    if (sc == 0.f) sc = 1.0f;
    float alpha = (*wscale) * sc;

    const float* bsh = reinterpret_cast<const float*>(smem + BIAS_OFF);
#pragma unroll
    for (int mt = 0; mt < 2; ++mt) {
#pragma unroll
        for (int nt = 0; nt < 8; ++nt) {
            int row = m0 + wm * 32 + mt * 16 + g;
            int lcol = wn * 64 + nt * 8 + t * 2;
            float b0 = bsh[lcol];
            float b1 = bsh[lcol + 1];
            float2 v0, v1;
            v0.x = acc[mt][nt][0] * alpha + b0;
            v0.y = acc[mt][nt][1] * alpha + b1;
            v1.x = acc[mt][nt][2] * alpha + b0;
            v1.y = acc[mt][nt][3] * alpha + b1;
            *reinterpret_cast<float2*>(out + (size_t)row * D_OUT + n0 + lcol) = v0;
            *reinterpret_cast<float2*>(out + (size_t)(row + 8) * D_OUT + n0 + lcol) = v1;
        }
    }
}

// ---------------- launcher --------------------------------------------------
extern "C" void kernel_launch(void* const* d_in, const int* in_sizes, int n_in,
                              void* d_out, int out_size) {
    const float* x    = (const float*)d_in[0];
    const int*   w    = (const int*)d_in[1];
    const float* ws   = (const float*)d_in[2];
    const float* bias = (const float*)d_in[3];
    float* out = (float*)d_out;

    cudaFuncSetAttribute(gemm_hmma, cudaFuncAttributeMaxDynamicSharedMemorySize,
                         SMEM_TOTAL);

    init_kernel<<<1, 1>>>();
    absmax_kernel<<<1024, 256>>>((const float4*)x, (N_TOK * D_IN) / 4);
    quant_kernel<<<2048, 256>>>((const float4*)x, (N_TOK * D_IN) / 4);
    wconv_kernel<<<1024, 256>>>((const int4*)w, (D_OUT * D_IN) / 4);

    dim3 grid(D_OUT / BN, N_TOK / BM);
    gemm_hmma<<<grid, NTHREADS, SMEM_TOTAL>>>(bias, ws, out);
}

// round 11
// speedup vs baseline: 1.1954x; 1.1954x over previous
// R11: interleave cp.async groups inside the ks/HMMA loop to kill the
// serial per-chunk cp-issue phase. 512 threads, CTA 128x256, 3 stages.
#include <cuda_runtime.h>
#include <cuda_bf16.h>
#include <cstdint>
#include <cstddef>

#define N_TOK 8192
#define D_IN  4096
#define D_OUT 4096

__device__ __align__(16) __nv_bfloat16 g_Xb[(size_t)N_TOK * D_IN];   // 64 MB
__device__ __align__(16) __nv_bfloat16 g_Wb[(size_t)D_OUT * D_IN];   // 32 MB
__device__ unsigned g_absmax_u;

// ---------------- helpers ---------------------------------------------------
__device__ __forceinline__ uint32_t smem_u32(const void* p) {
    uint32_t a;
    asm("{ .reg .u64 t; cvta.to.shared.u64 t, %1; cvt.u32.u64 %0, t; }"
        : "=r"(a) : "l"(p));
    return a;
}

__device__ __forceinline__ void cp16(uint32_t dst, const void* src) {
    asm volatile("cp.async.cg.shared.global [%0], [%1], 16;" :: "r"(dst), "l"(src));
}

__device__ __forceinline__ void hmma16816(float* c, const uint32_t* a, const uint32_t* b) {
    asm volatile(
        "mma.sync.aligned.m16n8k16.row.col.f32.bf16.bf16.f32 "
        "{%0,%1,%2,%3}, {%4,%5,%6,%7}, {%8,%9}, {%0,%1,%2,%3};"
        : "+f"(c[0]), "+f"(c[1]), "+f"(c[2]), "+f"(c[3])
        : "r"(a[0]), "r"(a[1]), "r"(a[2]), "r"(a[3]), "r"(b[0]), "r"(b[1]));
}

__device__ __forceinline__ void ldm_x4(uint32_t* r, uint32_t addr) {
    asm volatile(
        "ldmatrix.sync.aligned.m8n8.x4.shared.b16 {%0,%1,%2,%3}, [%4];"
        : "=r"(r[0]), "=r"(r[1]), "=r"(r[2]), "=r"(r[3]) : "r"(addr));
}

// ---------------- pre-kernels ----------------------------------------------
__global__ void init_kernel() { g_absmax_u = 0u; }

__global__ void absmax_kernel(const float4* __restrict__ x, int n4) {
    float m = 0.f;
    for (int i = blockIdx.x * blockDim.x + threadIdx.x; i < n4;
         i += gridDim.x * blockDim.x) {
        float4 v = x[i];
        m = fmaxf(m, fmaxf(fmaxf(fabsf(v.x), fabsf(v.y)),
                           fmaxf(fabsf(v.z), fabsf(v.w))));
    }
#pragma unroll
    for (int o = 16; o > 0; o >>= 1)
        m = fmaxf(m, __shfl_xor_sync(0xffffffffu, m, o));
    __shared__ float red[8];
    if ((threadIdx.x & 31) == 0) red[threadIdx.x >> 5] = m;
    __syncthreads();
    if (threadIdx.x == 0) {
        float v = red[0];
#pragma unroll
        for (int i = 1; i < 8; ++i) v = fmaxf(v, red[i]);
        atomicMax(&g_absmax_u, __float_as_uint(v));   // values >= 0: bit-monotone
    }
}

__global__ void quant_kernel(const float4* __restrict__ x, int n4) {
    float am = __uint_as_float(g_absmax_u);
    float s = __fdiv_rn(am, 127.0f);            // exact IEEE div, matches reference
    if (s == 0.f) s = 1.0f;
    for (int i = blockIdx.x * blockDim.x + threadIdx.x; i < n4;
         i += gridDim.x * blockDim.x) {
        float4 v = x[i];
        float a0 = fminf(fmaxf(rintf(__fdiv_rn(v.x, s)), -128.f), 127.f);
        float a1 = fminf(fmaxf(rintf(__fdiv_rn(v.y, s)), -128.f), 127.f);
        float a2 = fminf(fmaxf(rintf(__fdiv_rn(v.z, s)), -128.f), 127.f);
        float a3 = fminf(fmaxf(rintf(__fdiv_rn(v.w, s)), -128.f), 127.f);
        __nv_bfloat162 h0 = __floats2bfloat162_rn(a0, a1);
        __nv_bfloat162 h1 = __floats2bfloat162_rn(a2, a3);
        uint2 u;
        u.x = *reinterpret_cast<uint32_t*>(&h0);
        u.y = *reinterpret_cast<uint32_t*>(&h1);
        reinterpret_cast<uint2*>(g_Xb)[i] = u;
    }
}

__global__ void wconv_kernel(const int4* __restrict__ w, int n4) {
    for (int i = blockIdx.x * blockDim.x + threadIdx.x; i < n4;
         i += gridDim.x * blockDim.x) {
        int4 v = w[i];   // values in {-1, 0, 1}
        __nv_bfloat162 h0 = __floats2bfloat162_rn((float)v.x, (float)v.y);
        __nv_bfloat162 h1 = __floats2bfloat162_rn((float)v.z, (float)v.w);
        uint2 u;
        u.x = *reinterpret_cast<uint32_t*>(&h0);
        u.y = *reinterpret_cast<uint32_t*>(&h1);
        reinterpret_cast<uint2*>(g_Wb)[i] = u;
    }
}

// ---------------- bf16 GEMM: C[8192,4096] = Xb @ Wb^T -----------------------
#define BM 128
#define BN 256
#define BKE 64
#define BKB (BKE * 2)                     // 128 bytes per row per chunk
#define LDS_ROW 144                       // 128B data + 16B pad
#define A_STAGE (BM * LDS_ROW)            // 18432
#define B_STAGE (BN * LDS_ROW)            // 36864
#define STAGE_BYTES (A_STAGE + B_STAGE)   // 55296
#define STAGES 3
#define BIAS_OFF (STAGES * STAGE_BYTES)   // 165888
#define SMEM_TOTAL (BIAS_OFF + BN * 4)
#define NTHREADS 512

// one cp.async group: 512 ops, 1 per thread. g in [0,6); g<2 -> A, else B.
template <int G>
__device__ __forceinline__ void cp_group(uint32_t fas, const char* agf,
                                         const char* bgf, int tid) {
    if (G < 2) {
        int idx = G * NTHREADS + tid;            // 0..1023 -> A
        int row = idx >> 3, cc = idx & 7;
        cp16(fas + row * LDS_ROW + cc * 16,
             agf + (size_t)row * (D_IN * 2) + cc * 16);
    } else {
        int j = (G - 2) * NTHREADS + tid;        // 0..2047 -> B
        int row = j >> 3, cc = j & 7;
        cp16(fas + A_STAGE + row * LDS_ROW + cc * 16,
             bgf + (size_t)row * (D_IN * 2) + cc * 16);
    }
}

__device__ __forceinline__ void load_frags(uint32_t stg, uint32_t aAddrBase,
                                           uint32_t bAddrBase, int ks,
                                           uint32_t a[2][4], uint32_t b[8][2]) {
#pragma unroll
    for (int mt = 0; mt < 2; ++mt)
        ldm_x4(a[mt], stg + aAddrBase + mt * (16 * LDS_ROW) + ks * 32);
#pragma unroll
    for (int ntp = 0; ntp < 4; ++ntp) {
        uint32_t r[4];
        ldm_x4(r, stg + bAddrBase + ntp * (16 * LDS_ROW) + ks * 32);
        b[ntp * 2 + 0][0] = r[0];
        b[ntp * 2 + 0][1] = r[1];
        b[ntp * 2 + 1][0] = r[2];
        b[ntp * 2 + 1][1] = r[3];
    }
}

__global__ void __launch_bounds__(NTHREADS, 1)
gemm_hmma(const float* __restrict__ bias, const float* __restrict__ wscale,
          float* __restrict__ out) {
    extern __shared__ char smem[];
    const uint32_t sbase = smem_u32(smem);
    const int tid = threadIdx.x;
    const int wid = tid >> 5, lane = tid & 31;
    const int g = lane >> 2, t = lane & 3;
    const int wm = wid & 3, wn = wid >> 2;           // 4 warps in M, 4 in N
    const int m0 = blockIdx.y * BM, n0 = blockIdx.x * BN;

    const char* Ag = (const char*)g_Xb + (size_t)m0 * (D_IN * 2);
    const char* Bg = (const char*)g_Wb + (size_t)n0 * (D_IN * 2);

    if (tid < BN) {
        float bv = bias[n0 + tid];
        *reinterpret_cast<float*>(smem + BIAS_OFF + tid * 4) = bv;
    }

    const uint32_t aAddrBase =
        (uint32_t)((wm * 32 + (lane & 15)) * LDS_ROW + ((lane >> 4) * 16));
    const uint32_t bAddrBase =
        (uint32_t)(A_STAGE +
                   (wn * 64 + (lane & 7) + ((lane >> 4) * 8)) * LDS_ROW +
                   (((lane >> 3) & 1) * 16));

    float acc[2][8][4];
#pragma unroll
    for (int mt = 0; mt < 2; ++mt)
#pragma unroll
        for (int nt = 0; nt < 8; ++nt)
#pragma unroll
            for (int i = 0; i < 4; ++i) acc[mt][nt][i] = 0.f;

    // prologue: fill stages 0,1 completely
#pragma unroll
    for (int c = 0; c < 2; ++c) {
        uint32_t fas = sbase + c * STAGE_BYTES;
        const char* agf = Ag + (size_t)c * BKB;
        const char* bgf = Bg + (size_t)c * BKB;
        cp_group<0>(fas, agf, bgf, tid);
        cp_group<1>(fas, agf, bgf, tid);
        cp_group<2>(fas, agf, bgf, tid);
        cp_group<3>(fas, agf, bgf, tid);
        cp_group<4>(fas, agf, bgf, tid);
        cp_group<5>(fas, agf, bgf, tid);
        asm volatile("cp.async.commit_group;" ::: "memory");
    }

    uint32_t abuf[2][2][4], bbuf[2][8][2];

    const int NCHUNK = D_IN / BKE;   // 64
    for (int c = 0; c < NCHUNK; ++c) {
        asm volatile("cp.async.wait_group %0;" :: "n"(1));
        __syncthreads();

        const uint32_t stg = sbase + (c % STAGES) * STAGE_BYTES;
        const bool fill = (c + 2 < NCHUNK);
        const uint32_t fas = sbase + ((c + 2) % STAGES) * STAGE_BYTES;
        const char* agf = Ag + (size_t)(c + 2) * BKB;
        const char* bgf = Bg + (size_t)(c + 2) * BKB;

        // prime ks=0 fragments
        load_frags(stg, aAddrBase, bAddrBase, 0, abuf[0], bbuf[0]);
#pragma unroll
        for (int ks = 0; ks < 4; ++ks) {
            const int cur = ks & 1;
            if (ks < 3)
                load_frags(stg, aAddrBase, bAddrBase, ks + 1,
                           abuf[1 - cur], bbuf[1 - cur]);
            // interleaved global->smem prefetch for chunk c+2
            if (fill) {
                if (ks == 0) cp_group<0>(fas, agf, bgf, tid);
                if (ks == 1) cp_group<1>(fas, agf, bgf, tid);
                if (ks == 2) { cp_group<2>(fas, agf, bgf, tid);
                               cp_group<4>(fas, agf, bgf, tid); }
                if (ks == 3) { cp_group<3>(fas, agf, bgf, tid);
                               cp_group<5>(fas, agf, bgf, tid); }
            }
#pragma unroll
            for (int mt = 0; mt < 2; ++mt)
#pragma unroll
                for (int nt = 0; nt < 8; ++nt)
                    hmma16816(acc[mt][nt], abuf[cur][mt], bbuf[cur][nt]);
        }
        if (fill)
            asm volatile("cp.async.commit_group;" ::: "memory");
    }

    // epilogue: out = acc * (weight_scale * scale) + bias
    float am = __uint_as_float(g_absmax_u);
    float sc = __fdiv_rn(am, 127.0f);
    if (sc == 0.f) sc = 1.0f;
    float alpha = (*wscale) * sc;

    const float* bsh = reinterpret_cast<const float*>(smem + BIAS_OFF);
#pragma unroll
    for (int mt = 0; mt < 2; ++mt) {
#pragma unroll
        for (int nt = 0; nt < 8; ++nt) {
            int row = m0 + wm * 32 + mt * 16 + g;
            int lcol = wn * 64 + nt * 8 + t * 2;
            float b0 = bsh[lcol];
            float b1 = bsh[lcol + 1];
            float2 v0, v1;
            v0.x = acc[mt][nt][0] * alpha + b0;
            v0.y = acc[mt][nt][1] * alpha + b1;
            v1.x = acc[mt][nt][2] * alpha + b0;
            v1.y = acc[mt][nt][3] * alpha + b1;
            *reinterpret_cast<float2*>(out + (size_t)row * D_OUT + n0 + lcol) = v0;
            *reinterpret_cast<float2*>(out + (size_t)(row + 8) * D_OUT + n0 + lcol) = v1;
        }
    }
}

// ---------------- launcher --------------------------------------------------
extern "C" void kernel_launch(void* const* d_in, const int* in_sizes, int n_in,
                              void* d_out, int out_size) {
    const float* x    = (const float*)d_in[0];
    const int*   w    = (const int*)d_in[1];
    const float* ws   = (const float*)d_in[2];
    const float* bias = (const float*)d_in[3];
    float* out = (float*)d_out;

    cudaFuncSetAttribute(gemm_hmma, cudaFuncAttributeMaxDynamicSharedMemorySize,
                         SMEM_TOTAL);

    init_kernel<<<1, 1>>>();
    absmax_kernel<<<1024, 256>>>((const float4*)x, (N_TOK * D_IN) / 4);
    quant_kernel<<<2048, 256>>>((const float4*)x, (N_TOK * D_IN) / 4);
    wconv_kernel<<<1024, 256>>>((const int4*)w, (D_OUT * D_IN) / 4);

    dim3 grid(D_OUT / BN, N_TOK / BM);
    gemm_hmma<<<grid, NTHREADS, SMEM_TOTAL>>>(bias, ws, out);
}

// round 13
// speedup vs baseline: 1.3205x; 1.1047x over previous
// R12: 8-warp 64x64 warp tiles (best ldm:HMMA ratio) + R11's interleaved
// cp.async groups. 256 threads, CTA 128x256, 3-stage ring.
#include <cuda_runtime.h>
#include <cuda_bf16.h>
#include <cstdint>
#include <cstddef>

#define N_TOK 8192
#define D_IN  4096
#define D_OUT 4096

__device__ __align__(16) __nv_bfloat16 g_Xb[(size_t)N_TOK * D_IN];   // 64 MB
__device__ __align__(16) __nv_bfloat16 g_Wb[(size_t)D_OUT * D_IN];   // 32 MB
__device__ unsigned g_absmax_u;

// ---------------- helpers ---------------------------------------------------
__device__ __forceinline__ uint32_t smem_u32(const void* p) {
    uint32_t a;
    asm("{ .reg .u64 t; cvta.to.shared.u64 t, %1; cvt.u32.u64 %0, t; }"
        : "=r"(a) : "l"(p));
    return a;
}

__device__ __forceinline__ void cp16(uint32_t dst, const void* src) {
    asm volatile("cp.async.cg.shared.global [%0], [%1], 16;" :: "r"(dst), "l"(src));
}

__device__ __forceinline__ void hmma16816(float* c, const uint32_t* a, const uint32_t* b) {
    asm volatile(
        "mma.sync.aligned.m16n8k16.row.col.f32.bf16.bf16.f32 "
        "{%0,%1,%2,%3}, {%4,%5,%6,%7}, {%8,%9}, {%0,%1,%2,%3};"
        : "+f"(c[0]), "+f"(c[1]), "+f"(c[2]), "+f"(c[3])
        : "r"(a[0]), "r"(a[1]), "r"(a[2]), "r"(a[3]), "r"(b[0]), "r"(b[1]));
}

__device__ __forceinline__ void ldm_x4(uint32_t* r, uint32_t addr) {
    asm volatile(
        "ldmatrix.sync.aligned.m8n8.x4.shared.b16 {%0,%1,%2,%3}, [%4];"
        : "=r"(r[0]), "=r"(r[1]), "=r"(r[2]), "=r"(r[3]) : "r"(addr));
}

// ---------------- pre-kernels ----------------------------------------------
__global__ void init_kernel() { g_absmax_u = 0u; }

__global__ void absmax_kernel(const float4* __restrict__ x, int n4) {
    float m = 0.f;
    for (int i = blockIdx.x * blockDim.x + threadIdx.x; i < n4;
         i += gridDim.x * blockDim.x) {
        float4 v = x[i];
        m = fmaxf(m, fmaxf(fmaxf(fabsf(v.x), fabsf(v.y)),
                           fmaxf(fabsf(v.z), fabsf(v.w))));
    }
#pragma unroll
    for (int o = 16; o > 0; o >>= 1)
        m = fmaxf(m, __shfl_xor_sync(0xffffffffu, m, o));
    __shared__ float red[8];
    if ((threadIdx.x & 31) == 0) red[threadIdx.x >> 5] = m;
    __syncthreads();
    if (threadIdx.x == 0) {
        float v = red[0];
#pragma unroll
        for (int i = 1; i < 8; ++i) v = fmaxf(v, red[i]);
        atomicMax(&g_absmax_u, __float_as_uint(v));   // values >= 0: bit-monotone
    }
}

__global__ void quant_kernel(const float4* __restrict__ x, int n4) {
    float am = __uint_as_float(g_absmax_u);
    float s = __fdiv_rn(am, 127.0f);            // exact IEEE div, matches reference
    if (s == 0.f) s = 1.0f;
    for (int i = blockIdx.x * blockDim.x + threadIdx.x; i < n4;
         i += gridDim.x * blockDim.x) {
        float4 v = x[i];
        float a0 = fminf(fmaxf(rintf(__fdiv_rn(v.x, s)), -128.f), 127.f);
        float a1 = fminf(fmaxf(rintf(__fdiv_rn(v.y, s)), -128.f), 127.f);
        float a2 = fminf(fmaxf(rintf(__fdiv_rn(v.z, s)), -128.f), 127.f);
        float a3 = fminf(fmaxf(rintf(__fdiv_rn(v.w, s)), -128.f), 127.f);
        __nv_bfloat162 h0 = __floats2bfloat162_rn(a0, a1);
        __nv_bfloat162 h1 = __floats2bfloat162_rn(a2, a3);
        uint2 u;
        u.x = *reinterpret_cast<uint32_t*>(&h0);
        u.y = *reinterpret_cast<uint32_t*>(&h1);
        reinterpret_cast<uint2*>(g_Xb)[i] = u;
    }
}

__global__ void wconv_kernel(const int4* __restrict__ w, int n4) {
    for (int i = blockIdx.x * blockDim.x + threadIdx.x; i < n4;
         i += gridDim.x * blockDim.x) {
        int4 v = w[i];   // values in {-1, 0, 1}
        __nv_bfloat162 h0 = __floats2bfloat162_rn((float)v.x, (float)v.y);
        __nv_bfloat162 h1 = __floats2bfloat162_rn((float)v.z, (float)v.w);
        uint2 u;
        u.x = *reinterpret_cast<uint32_t*>(&h0);
        u.y = *reinterpret_cast<uint32_t*>(&h1);
        reinterpret_cast<uint2*>(g_Wb)[i] = u;
    }
}

// ---------------- bf16 GEMM: C[8192,4096] = Xb @ Wb^T -----------------------
#define BM 128
#define BN 256
#define BKE 64
#define BKB (BKE * 2)                     // 128 bytes per row per chunk
#define LDS_ROW 144                       // 128B data + 16B pad
#define A_STAGE (BM * LDS_ROW)            // 18432
#define B_STAGE (BN * LDS_ROW)            // 36864
#define STAGE_BYTES (A_STAGE + B_STAGE)   // 55296
#define STAGES 3
#define BIAS_OFF (STAGES * STAGE_BYTES)   // 165888
#define SMEM_TOTAL (BIAS_OFF + BN * 4)
#define NTHREADS 256

// one cp.async group: 256 ops, 1/thread. G in [0,12): G<4 -> A, else B.
template <int G>
__device__ __forceinline__ void cp_group(uint32_t fas, const char* agf,
                                         const char* bgf, int tid) {
    if (G < 4) {
        int idx = G * NTHREADS + tid;            // 0..1023 -> A
        int row = idx >> 3, cc = idx & 7;
        cp16(fas + row * LDS_ROW + cc * 16,
             agf + (size_t)row * (D_IN * 2) + cc * 16);
    } else {
        int j = (G - 4) * NTHREADS + tid;        // 0..2047 -> B
        int row = j >> 3, cc = j & 7;
        cp16(fas + A_STAGE + row * LDS_ROW + cc * 16,
             bgf + (size_t)row * (D_IN * 2) + cc * 16);
    }
}

__device__ __forceinline__ void load_frags(uint32_t stg, uint32_t aAddrBase,
                                           uint32_t bAddrBase, int ks,
                                           uint32_t a[4][4], uint32_t b[8][2]) {
#pragma unroll
    for (int mt = 0; mt < 4; ++mt)
        ldm_x4(a[mt], stg + aAddrBase + mt * (16 * LDS_ROW) + ks * 32);
#pragma unroll
    for (int ntp = 0; ntp < 4; ++ntp) {
        uint32_t r[4];
        ldm_x4(r, stg + bAddrBase + ntp * (16 * LDS_ROW) + ks * 32);
        b[ntp * 2 + 0][0] = r[0];
        b[ntp * 2 + 0][1] = r[1];
        b[ntp * 2 + 1][0] = r[2];
        b[ntp * 2 + 1][1] = r[3];
    }
}

__global__ void __launch_bounds__(NTHREADS, 1)
gemm_hmma(const float* __restrict__ bias, const float* __restrict__ wscale,
          float* __restrict__ out) {
    extern __shared__ char smem[];
    const uint32_t sbase = smem_u32(smem);
    const int tid = threadIdx.x;
    const int wid = tid >> 5, lane = tid & 31;
    const int g = lane >> 2, t = lane & 3;
    const int wm = wid & 1, wn = wid >> 1;           // 2 warps in M, 4 in N
    const int m0 = blockIdx.y * BM, n0 = blockIdx.x * BN;

    const char* Ag = (const char*)g_Xb + (size_t)m0 * (D_IN * 2);
    const char* Bg = (const char*)g_Wb + (size_t)n0 * (D_IN * 2);

    if (tid < BN) {
        float bv = bias[n0 + tid];
        *reinterpret_cast<float*>(smem + BIAS_OFF + tid * 4) = bv;
    }

    const uint32_t aAddrBase =
        (uint32_t)((wm * 64 + (lane & 15)) * LDS_ROW + ((lane >> 4) * 16));
    const uint32_t bAddrBase =
        (uint32_t)(A_STAGE +
                   (wn * 64 + (lane & 7) + ((lane >> 4) * 8)) * LDS_ROW +
                   (((lane >> 3) & 1) * 16));

    float acc[4][8][4];
#pragma unroll
    for (int mt = 0; mt < 4; ++mt)
#pragma unroll
        for (int nt = 0; nt < 8; ++nt)
#pragma unroll
            for (int i = 0; i < 4; ++i) acc[mt][nt][i] = 0.f;

    // prologue: fill stages 0,1 completely
#pragma unroll
    for (int c = 0; c < 2; ++c) {
        uint32_t fas = sbase + c * STAGE_BYTES;
        const char* agf = Ag + (size_t)c * BKB;
        const char* bgf = Bg + (size_t)c * BKB;
        cp_group<0>(fas, agf, bgf, tid);  cp_group<1>(fas, agf, bgf, tid);
        cp_group<2>(fas, agf, bgf, tid);  cp_group<3>(fas, agf, bgf, tid);
        cp_group<4>(fas, agf, bgf, tid);  cp_group<5>(fas, agf, bgf, tid);
        cp_group<6>(fas, agf, bgf, tid);  cp_group<7>(fas, agf, bgf, tid);
        cp_group<8>(fas, agf, bgf, tid);  cp_group<9>(fas, agf, bgf, tid);
        cp_group<10>(fas, agf, bgf, tid); cp_group<11>(fas, agf, bgf, tid);
        asm volatile("cp.async.commit_group;" ::: "memory");
    }

    uint32_t abuf[2][4][4], bbuf[2][8][2];

    const int NCHUNK = D_IN / BKE;   // 64
    for (int c = 0; c < NCHUNK; ++c) {
        asm volatile("cp.async.wait_group %0;" :: "n"(1));
        __syncthreads();

        const uint32_t stg = sbase + (c % STAGES) * STAGE_BYTES;
        const bool fill = (c + 2 < NCHUNK);
        const uint32_t fas = sbase + ((c + 2) % STAGES) * STAGE_BYTES;
        const char* agf = Ag + (size_t)(c + 2) * BKB;
        const char* bgf = Bg + (size_t)(c + 2) * BKB;

        load_frags(stg, aAddrBase, bAddrBase, 0, abuf[0], bbuf[0]);
#pragma unroll
        for (int ks = 0; ks < 4; ++ks) {
            const int cur = ks & 1;
            if (ks < 3)
                load_frags(stg, aAddrBase, bAddrBase, ks + 1,
                           abuf[1 - cur], bbuf[1 - cur]);
            if (fill) {   // 3 cp groups per ks, hidden under the 32 HMMAs below
                if (ks == 0) { cp_group<0>(fas, agf, bgf, tid);
                               cp_group<4>(fas, agf, bgf, tid);
                               cp_group<5>(fas, agf, bgf, tid); }
                if (ks == 1) { cp_group<1>(fas, agf, bgf, tid);
                               cp_group<6>(fas, agf, bgf, tid);
                               cp_group<7>(fas, agf, bgf, tid); }
                if (ks == 2) { cp_group<2>(fas, agf, bgf, tid);
                               cp_group<8>(fas, agf, bgf, tid);
                               cp_group<9>(fas, agf, bgf, tid); }
                if (ks == 3) { cp_group<3>(fas, agf, bgf, tid);
                               cp_group<10>(fas, agf, bgf, tid);
                               cp_group<11>(fas, agf, bgf, tid); }
            }
#pragma unroll
            for (int mt = 0; mt < 4; ++mt)
#pragma unroll
                for (int nt = 0; nt < 8; ++nt)
                    hmma16816(acc[mt][nt], abuf[cur][mt], bbuf[cur][nt]);
        }
        if (fill)
            asm volatile("cp.async.commit_group;" ::: "memory");
    }

    // epilogue: out = acc * (weight_scale * scale) + bias
    float am = __uint_as_float(g_absmax_u);
    float sc = __fdiv_rn(am, 127.0f);
    if (sc == 0.f) sc = 1.0f;
    float alpha = (*wscale) * sc;

    const float* bsh = reinterpret_cast<const float*>(smem + BIAS_OFF);
#pragma unroll
    for (int mt = 0; mt < 4; ++mt) {
#pragma unroll
        for (int nt = 0; nt < 8; ++nt) {
            int row = m0 + wm * 64 + mt * 16 + g;
            int lcol = wn * 64 + nt * 8 + t * 2;
            float b0 = bsh[lcol];
            float b1 = bsh[lcol + 1];
            float2 v0, v1;
            v0.x = acc[mt][nt][0] * alpha + b0;
            v0.y = acc[mt][nt][1] * alpha + b1;
            v1.x = acc[mt][nt][2] * alpha + b0;
            v1.y = acc[mt][nt][3] * alpha + b1;
            *reinterpret_cast<float2*>(out + (size_t)row * D_OUT + n0 + lcol) = v0;
            *reinterpret_cast<float2*>(out + (size_t)(row + 8) * D_OUT + n0 + lcol) = v1;
        }
    }
}

// ---------------- launcher --------------------------------------------------
extern "C" void kernel_launch(void* const* d_in, const int* in_sizes, int n_in,
                              void* d_out, int out_size) {
    const float* x    = (const float*)d_in[0];
    const int*   w    = (const int*)d_in[1];
    const float* ws   = (const float*)d_in[2];
    const float* bias = (const float*)d_in[3];
    float* out = (float*)d_out;

    cudaFuncSetAttribute(gemm_hmma, cudaFuncAttributeMaxDynamicSharedMemorySize,
                         SMEM_TOTAL);

    init_kernel<<<1, 1>>>();
    absmax_kernel<<<1024, 256>>>((const float4*)x, (N_TOK * D_IN) / 4);
    quant_kernel<<<2048, 256>>>((const float4*)x, (N_TOK * D_IN) / 4);
    wconv_kernel<<<1024, 256>>>((const int4*)w, (D_OUT * D_IN) / 4);

    dim3 grid(D_OUT / BN, N_TOK / BM);
    gemm_hmma<<<grid, NTHREADS, SMEM_TOTAL>>>(bias, ws, out);
}